// round 3
// baseline (speedup 1.0000x reference)
#include <cuda_runtime.h>
#include <cuda_bf16.h>
#include <math.h>

// Problem shapes (fixed for this dataset)
#define KDIM 32
#define DDIM 32
#define N_I 5000
#define N_J 5000
#define M_I 2500
#define M_J 2500
#define N_EDGES 200000
#define BM 64
#define BN 64
#define PAD_M 2560          // 40 * 64, padded sampled-row count
#define EPSV 1e-6f
#define C0 (32.0f * EPSV * EPSV)

// ---------------- scratch (static device globals; no allocation) -------------
__device__ float g_SZi[KDIM * N_I];      // softmax(Z_i) (k, n_i)
__device__ float g_SZj[KDIM * N_J];      // softmax(Z_j) (k, n_j)
__device__ float g_T[KDIM * KDIM];       // T[a][b] = sum_m Z[a,m] Z[b,m] G[m,b]
__device__ float g_s[KDIM];              // s[b] = sum_m Z[b,m] G[m,b]
__device__ float g_AZC[DDIM * KDIM];     // AZC (d, k)
__device__ float g_Xi[N_I * DDIM];       // (AZC @ SZi)^T, row-major per node
__device__ float g_qi[N_I];              // ||x||^2 + 2 eps sum(x)
__device__ float g_Xj[N_J * DDIM];
__device__ float g_qj[N_J];              // ||x||^2 - 2 eps sum(x)
__device__ float g_XiS[PAD_M * DDIM];    // gathered + padded sampled rows (i)
__device__ float g_qiS[PAD_M];
__device__ float g_biS[PAD_M];           // beta[sample_i]
__device__ float g_XjS[PAD_M * DDIM];
__device__ float g_qjS[PAD_M];
__device__ float g_gjS[PAD_M];           // gamma[sample_j]
__device__ double g_mat;
__device__ double g_links;

// ---------------- k1: column softmax of Z_i and Z_j --------------------------
__global__ void k_softmax(const float* __restrict__ Zi, const float* __restrict__ Zj) {
    int c = blockIdx.x * blockDim.x + threadIdx.x;
    if (c >= N_I + N_J) return;
    const float* src; float* dst; int n, cc;
    if (c < N_I) { src = Zi; dst = g_SZi; n = N_I; cc = c; }
    else         { src = Zj; dst = g_SZj; n = N_J; cc = c - N_I; }
    float v[KDIM];
    float mx = -1e30f;
#pragma unroll
    for (int a = 0; a < KDIM; a++) { v[a] = src[a * n + cc]; mx = fmaxf(mx, v[a]); }
    float sum = 0.f;
#pragma unroll
    for (int a = 0; a < KDIM; a++) { v[a] = __expf(v[a] - mx); sum += v[a]; }
    float inv = 1.f / sum;
#pragma unroll
    for (int a = 0; a < KDIM; a++) dst[a * n + cc] = v[a] * inv;
}

// ---------------- k2: zero accumulators --------------------------------------
__global__ void k_init() {
    int t = threadIdx.x;
    if (t < KDIM * KDIM) g_T[t] = 0.f;
    if (t < KDIM) g_s[t] = 0.f;
    if (t == 0) { g_mat = 0.0; g_links = 0.0; }
}

// ---------------- k3: gate statistics s[b], T[a][b] ---------------------------
__global__ void k_stats(const int* __restrict__ si, const int* __restrict__ sj,
                        const float* __restrict__ Gate) {
    int gwarp = (blockIdx.x * blockDim.x + threadIdx.x) >> 5;
    int lane = threadIdx.x & 31;
    int nwarps = (gridDim.x * blockDim.x) >> 5;

    float sacc = 0.f;
    float tacc[KDIM];
#pragma unroll
    for (int a = 0; a < KDIM; a++) tacc[a] = 0.f;

    for (int m = gwarp; m < M_I + M_J; m += nwarps) {
        int idx; const float* SZ; int n;
        if (m < M_I) { idx = si[m]; SZ = g_SZi; n = N_I; }
        else         { idx = sj[m - M_I]; SZ = g_SZj; n = N_J; }
        float z = SZ[lane * n + idx];
        float gt = Gate[idx * KDIM + lane];   // faithful: sample_j indexes Gate w/o offset
        float g = 1.f / (1.f + __expf(-gt));
        float w = z * g;
        sacc += w;
#pragma unroll
        for (int a = 0; a < KDIM; a++) {
            float za = __shfl_sync(0xffffffffu, z, a);
            tacc[a] = fmaf(za, w, tacc[a]);
        }
    }
    atomicAdd(&g_s[lane], sacc);
#pragma unroll
    for (int a = 0; a < KDIM; a++) atomicAdd(&g_T[a * KDIM + lane], tacc[a]);
}

// ---------------- k4: AZC = A @ (T / s) ---------------------------------------
__global__ void k_azc(const float* __restrict__ A) {
    __shared__ float Ms[KDIM][KDIM];
    __shared__ float ss[KDIM];
    int t = threadIdx.x;
    if (t < KDIM) ss[t] = g_s[t];
    __syncthreads();
    {
        int a = t >> 5, b = t & 31;
        Ms[a][b] = g_T[t] / ss[b];
    }
    __syncthreads();
    int dd = t >> 5, b = t & 31;
    float acc = 0.f;
#pragma unroll
    for (int a = 0; a < KDIM; a++) acc = fmaf(A[dd * KDIM + a], Ms[a][b], acc);
    g_AZC[t] = acc;
}

// ---------------- k5: per-node latent positions + norms -----------------------
__global__ void k_xfull() {
    __shared__ float AZ[DDIM][KDIM];
    for (int e = threadIdx.x; e < DDIM * KDIM; e += blockDim.x)
        AZ[e >> 5][e & 31] = g_AZC[e];
    __syncthreads();

    int c = blockIdx.x * blockDim.x + threadIdx.x;
    if (c >= N_I + N_J) return;
    const float* SZ; float* X; float* q; int n, cc, side;
    if (c < N_I) { SZ = g_SZi; X = g_Xi; q = g_qi; n = N_I; cc = c; side = 0; }
    else         { SZ = g_SZj; X = g_Xj; q = g_qj; n = N_J; cc = c - N_I; side = 1; }

    float x[DDIM];
#pragma unroll
    for (int dd = 0; dd < DDIM; dd++) x[dd] = 0.f;
#pragma unroll
    for (int a = 0; a < KDIM; a++) {
        float z = SZ[a * n + cc];
#pragma unroll
        for (int dd = 0; dd < DDIM; dd++) x[dd] = fmaf(AZ[dd][a], z, x[dd]);
    }
    float s2 = 0.f, s1 = 0.f;
#pragma unroll
    for (int dd = 0; dd < DDIM; dd++) {
        s2 = fmaf(x[dd], x[dd], s2);
        s1 += x[dd];
        X[cc * DDIM + dd] = x[dd];
    }
    q[cc] = side == 0 ? (s2 + 2.f * EPSV * s1) : (s2 - 2.f * EPSV * s1);
}

// ---------------- k6: gather sampled rows (+padding) --------------------------
__global__ void k_gather(const int* __restrict__ si, const int* __restrict__ sj,
                         const float* __restrict__ beta, const float* __restrict__ gamma) {
    int t = blockIdx.x * blockDim.x + threadIdx.x;
    if (t >= 2 * PAD_M) return;
    int side = t / PAD_M;
    int p = t - side * PAD_M;
    if (side == 0) {
        if (p < M_I) {
            int idx = si[p];
            const float4* s4 = (const float4*)&g_Xi[idx * DDIM];
            float4* d4 = (float4*)&g_XiS[p * DDIM];
#pragma unroll
            for (int w = 0; w < DDIM / 4; w++) d4[w] = s4[w];
            g_qiS[p] = g_qi[idx];
            g_biS[p] = beta[idx];
        } else {
            float4* d4 = (float4*)&g_XiS[p * DDIM];
            float4 z4 = make_float4(0.f, 0.f, 0.f, 0.f);
#pragma unroll
            for (int w = 0; w < DDIM / 4; w++) d4[w] = z4;
            g_qiS[p] = 1e30f;
            g_biS[p] = 0.f;
        }
    } else {
        if (p < M_J) {
            int idx = sj[p];
            const float4* s4 = (const float4*)&g_Xj[idx * DDIM];
            float4* d4 = (float4*)&g_XjS[p * DDIM];
#pragma unroll
            for (int w = 0; w < DDIM / 4; w++) d4[w] = s4[w];
            g_qjS[p] = g_qj[idx];
            g_gjS[p] = gamma[idx];
        } else {
            float4* d4 = (float4*)&g_XjS[p * DDIM];
            float4 z4 = make_float4(0.f, 0.f, 0.f, 0.f);
#pragma unroll
            for (int w = 0; w < DDIM / 4; w++) d4[w] = z4;
            g_qjS[p] = 1e30f;
            g_gjS[p] = 0.f;
        }
    }
}

// ---------------- k7: dominant pairwise exp-distance sum ----------------------
// GEMM-shaped: 64x64 tile per block, 256 threads, 4x4 microtile, K=32 resident.
__global__ void __launch_bounds__(256) k_pair() {
    __shared__ float As[KDIM][BM];
    __shared__ float Bs[KDIM][BN];
    __shared__ float qis[BM], bis[BM], qjs[BN], gjs[BN];

    int bi0 = blockIdx.y * BM;
    int bj0 = blockIdx.x * BN;
    int t = threadIdx.x;

    for (int e = t; e < BM * KDIM; e += 256) {
        int r = e >> 5, kk = e & 31;
        As[kk][r] = g_XiS[(bi0 + r) * DDIM + kk];
    }
    for (int e = t; e < BN * KDIM; e += 256) {
        int r = e >> 5, kk = e & 31;
        Bs[kk][r] = g_XjS[(bj0 + r) * DDIM + kk];
    }
    if (t < BM) { qis[t] = g_qiS[bi0 + t]; bis[t] = g_biS[bi0 + t]; }
    if (t < BN) { qjs[t] = g_qjS[bj0 + t]; gjs[t] = g_gjS[bj0 + t]; }
    __syncthreads();

    int tx = t & 15, ty = t >> 4;
    float acc[4][4];
#pragma unroll
    for (int r = 0; r < 4; r++)
#pragma unroll
        for (int c = 0; c < 4; c++) acc[r][c] = 0.f;

#pragma unroll
    for (int kk = 0; kk < KDIM; kk++) {
        float4 a4 = *(const float4*)&As[kk][ty * 4];
        float4 b4 = *(const float4*)&Bs[kk][tx * 4];
        float av[4] = {a4.x, a4.y, a4.z, a4.w};
        float bv[4] = {b4.x, b4.y, b4.z, b4.w};
#pragma unroll
        for (int r = 0; r < 4; r++)
#pragma unroll
            for (int c = 0; c < 4; c++) acc[r][c] = fmaf(av[r], bv[c], acc[r][c]);
    }

    float sum = 0.f;
#pragma unroll
    for (int r = 0; r < 4; r++) {
        float qa = qis[ty * 4 + r];
        float ba = bis[ty * 4 + r];
#pragma unroll
        for (int c = 0; c < 4; c++) {
            float d2 = qa + qjs[tx * 4 + c] - 2.f * acc[r][c] + C0;
            d2 = fmaxf(d2, 0.f);
            sum += __expf(ba + gjs[tx * 4 + c] - sqrtf(d2));
        }
    }

#pragma unroll
    for (int o = 16; o; o >>= 1) sum += __shfl_down_sync(0xffffffffu, sum, o);
    __shared__ float red[8];
    if ((t & 31) == 0) red[t >> 5] = sum;
    __syncthreads();
    if (t == 0) {
        float s = 0.f;
#pragma unroll
        for (int i = 0; i < 8; i++) s += red[i];
        atomicAdd(&g_mat, (double)s);
    }
}

// ---------------- k8: sparse edge term ----------------------------------------
__global__ void __launch_bounds__(256) k_edges(const int* __restrict__ spi,
                                               const int* __restrict__ spj,
                                               const float* __restrict__ beta,
                                               const float* __restrict__ gamma) {
    int e = blockIdx.x * blockDim.x + threadIdx.x;
    float sum = 0.f;
    if (e < N_EDGES) {
        int ii = spi[e];
        int jj = spj[e];
        const float4* xa = (const float4*)&g_Xi[ii * DDIM];
        const float4* xb = (const float4*)&g_Xj[jj * DDIM];
        float dot = 0.f;
#pragma unroll
        for (int w = 0; w < DDIM / 4; w++) {
            float4 a = xa[w], b = xb[w];
            dot = fmaf(a.x, b.x, dot);
            dot = fmaf(a.y, b.y, dot);
            dot = fmaf(a.z, b.z, dot);
            dot = fmaf(a.w, b.w, dot);
        }
        float d2 = g_qi[ii] + g_qj[jj] - 2.f * dot + C0;
        d2 = fmaxf(d2, 0.f);
        sum = beta[ii] + gamma[jj] - sqrtf(d2);
    }
#pragma unroll
    for (int o = 16; o; o >>= 1) sum += __shfl_down_sync(0xffffffffu, sum, o);
    __shared__ float red[8];
    int t = threadIdx.x;
    if ((t & 31) == 0) red[t >> 5] = sum;
    __syncthreads();
    if (t == 0) {
        float s = 0.f;
#pragma unroll
        for (int i = 0; i < 8; i++) s += red[i];
        atomicAdd(&g_links, (double)s);
    }
}

// ---------------- k9: final scalar --------------------------------------------
__global__ void k_final(float* out) {
    out[0] = (float)(g_links - g_mat);
}

// ---------------- launcher -----------------------------------------------------
extern "C" void kernel_launch(void* const* d_in, const int* in_sizes, int n_in,
                              void* d_out, int out_size) {
    const float* beta  = (const float*)d_in[0];
    const float* gamma = (const float*)d_in[1];
    const float* A     = (const float*)d_in[2];
    const float* Z_i   = (const float*)d_in[3];
    const float* Z_j   = (const float*)d_in[4];
    const float* Gate  = (const float*)d_in[5];
    const int* si      = (const int*)d_in[6];
    const int* sj      = (const int*)d_in[7];
    const int* spi     = (const int*)d_in[8];
    const int* spj     = (const int*)d_in[9];
    float* out = (float*)d_out;

    // 1. softmaxes over k per column
    k_softmax<<<(N_I + N_J + 255) / 256, 256>>>(Z_i, Z_j);
    // 2. zero accumulators
    k_init<<<1, 1024>>>();
    // 3. gate statistics (s, T)
    k_stats<<<40, 128>>>(si, sj, Gate);
    // 4. AZC = A @ (T / s)
    k_azc<<<1, 1024>>>(A);
    // 5. per-node latent positions
    k_xfull<<<(N_I + N_J + 255) / 256, 256>>>();
    // 6. gather sampled rows + padding
    k_gather<<<(2 * PAD_M + 255) / 256, 256>>>(si, sj, beta, gamma);
    // 7. dense pairwise block (dominant)
    dim3 pg(PAD_M / BN, PAD_M / BM);
    k_pair<<<pg, 256>>>();
    // 8. edge term
    k_edges<<<(N_EDGES + 255) / 256, 256>>>(spi, spj, beta, gamma);
    // 9. final scalar
    k_final<<<1, 1>>>(out);
}